// round 4
// baseline (speedup 1.0000x reference)
#include <cuda_runtime.h>
#include <cuda_bf16.h>
#include <cstdint>
#include <math.h>

#define NTOK 4096
#define HDIM 4096
#define FDIM 14336
#define NEXP 8
#define NR   8
#define LSCALE 2.0f

// ---------------------------------------------------------------------------
// Scratch (__device__ globals; allocation-free rule)
// ---------------------------------------------------------------------------
__device__ int8_t g_x1[(size_t)NTOK * HDIM];
__device__ int8_t g_x2[(size_t)NTOK * HDIM];
__device__ int8_t g_b1q1[(size_t)FDIM * HDIM];
__device__ int8_t g_b1q2[(size_t)FDIM * HDIM];
__device__ int8_t g_b3q1[(size_t)FDIM * HDIM];
__device__ int8_t g_b3q2[(size_t)FDIM * HDIM];
__device__ int8_t g_b2q1[(size_t)HDIM * FDIM];
__device__ int8_t g_b2q2[(size_t)HDIM * FDIM];
__device__ int8_t g_aq1[(size_t)NTOK * FDIM];
__device__ int8_t g_aq2[(size_t)NTOK * FDIM];
__device__ float  g_h1 [(size_t)NTOK * FDIM];   // x@w1 gate (fp32)
__device__ float  g_a2f[(size_t)NTOK * FDIM];   // silu(h1)*h3 (fp32)
__device__ float  g_sb1[FDIM];                  // per-row steps (weights)
__device__ float  g_sb3[FDIM];
__device__ float  g_sb2[HDIM];
__device__ float  g_sax[NTOK];                  // per-token step of x
__device__ float  g_sa2[NTOK];                  // per-token step of a2
__device__ float  g_c[NTOK * NEXP * NR];        // LoRA coefficients

// ---------------------------------------------------------------------------
// Asm helpers (sm_80-level features: legal on plain sm_103 target)
// ---------------------------------------------------------------------------
__device__ __forceinline__ uint32_t smem_u32(const void* p) {
    uint32_t a;
    asm("{ .reg .u64 t; cvta.to.shared.u64 t, %1; cvt.u32.u64 %0, t; }" : "=r"(a) : "l"(p));
    return a;
}

#define CP16(dst, src) \
    asm volatile("cp.async.cg.shared.global [%0], [%1], 16;" :: "r"(dst), "l"(src))
#define CP_COMMIT() asm volatile("cp.async.commit_group;" ::: "memory")
#define CP_WAIT1()  asm volatile("cp.async.wait_group 1;" ::: "memory")

#define LDSM4(r0, r1, r2, r3, a) \
    asm volatile("ldmatrix.sync.aligned.m8n8.x4.shared.b16 {%0,%1,%2,%3}, [%4];" \
        : "=r"(r0), "=r"(r1), "=r"(r2), "=r"(r3) : "r"(a))

#define MMA_S8(c, a0, a1, a2, a3, b0, b1) \
    asm volatile("mma.sync.aligned.m16n8k32.row.col.s32.s8.s8.s32 " \
        "{%0,%1,%2,%3}, {%4,%5,%6,%7}, {%8,%9}, {%0,%1,%2,%3};" \
        : "+r"((c)[0]), "+r"((c)[1]), "+r"((c)[2]), "+r"((c)[3]) \
        : "r"(a0), "r"(a1), "r"(a2), "r"(a3), "r"(b0), "r"(b1))

// ---------------------------------------------------------------------------
// Scale-prep kernels
// ---------------------------------------------------------------------------
__global__ void zero_kernel(float* p, int n) {
    int i = blockIdx.x * 256 + threadIdx.x;
    if (i < n) p[i] = 0.f;
}

// column max |W[:,c]| of W [K,N] -> cm[c] (as uint-ordered float, via atomicMax)
__global__ void __launch_bounds__(256) colmax_kernel(
    const float* __restrict__ W, float* __restrict__ cm, int K, int N)
{
    int c  = blockIdx.x * 256 + threadIdx.x;
    int k0 = blockIdx.y * 512;
    float m = 0.f;
    const float* p = W + (size_t)k0 * N + c;
    for (int k = 0; k < 512; k++) m = fmaxf(m, fabsf(p[(size_t)k * N]));
    atomicMax((unsigned int*)&cm[c], __float_as_uint(m));
}

// in-place: cm (max) -> step = max(cm, tiny)/127
__global__ void finalize_scale_kernel(float* s, int n) {
    int i = blockIdx.x * 256 + threadIdx.x;
    if (i < n) s[i] = fmaxf(s[i], 1e-30f) * (1.f / 127.f);
}

// W [K,N] fp32 -> two int8 slices [N,K] (transpose + quantize, per-row step)
__global__ void __launch_bounds__(256) transpose_quant_kernel(
    const float* __restrict__ W, int8_t* __restrict__ q1, int8_t* __restrict__ q2,
    const float* __restrict__ stepN, int K, int N)
{
    __shared__ float t[32][33];
    int n0 = blockIdx.x * 32, k0 = blockIdx.y * 32;
    int tx = threadIdx.x & 31, ty = threadIdx.x >> 5;
    #pragma unroll
    for (int j = 0; j < 4; j++)
        t[ty + 8 * j][tx] = W[(size_t)(k0 + ty + 8 * j) * N + n0 + tx];
    __syncthreads();
    #pragma unroll
    for (int j = 0; j < 4; j++) {
        int r = ty + 8 * j;
        int n = n0 + r;
        float s  = stepN[n];
        float v  = t[tx][r];
        int   i1 = __float2int_rn(v / s);
        float rr = v - (float)i1 * s;
        int   i2 = __float2int_rn(rr * (254.f / s));
        size_t o = (size_t)n * K + k0 + tx;
        q1[o] = (int8_t)i1;
        q2[o] = (int8_t)i2;
    }
}

// row-quantize x [N,H]: compute step per row, write slices + step
__global__ void __launch_bounds__(256) quant_x_kernel(const float* __restrict__ x)
{
    int n = blockIdx.x;
    const float* xr = x + (size_t)n * HDIM;
    __shared__ float red[8];
    float m = 0.f;
    for (int i = threadIdx.x; i < HDIM / 4; i += 256) {
        float4 v = ((const float4*)xr)[i];
        m = fmaxf(m, fmaxf(fmaxf(fabsf(v.x), fabsf(v.y)), fmaxf(fabsf(v.z), fabsf(v.w))));
    }
    #pragma unroll
    for (int o = 16; o; o >>= 1) m = fmaxf(m, __shfl_xor_sync(0xffffffffu, m, o));
    if ((threadIdx.x & 31) == 0) red[threadIdx.x >> 5] = m;
    __syncthreads();
    m = red[threadIdx.x & 7];
    #pragma unroll
    for (int o = 4; o; o >>= 1) m = fmaxf(m, __shfl_xor_sync(0xffffffffu, m, o));
    float step = fmaxf(m, 1e-30f) * (1.f / 127.f);
    if (threadIdx.x == 0) g_sax[n] = step;
    float inv1 = 1.f / step, inv2 = 254.f / step;
    for (int i = threadIdx.x; i < HDIM / 4; i += 256) {
        float4 v = ((const float4*)xr)[i];
        int a0 = __float2int_rn(v.x * inv1), a1 = __float2int_rn(v.y * inv1);
        int a2 = __float2int_rn(v.z * inv1), a3 = __float2int_rn(v.w * inv1);
        char4 c1 = make_char4((char)a0, (char)a1, (char)a2, (char)a3);
        char4 c2 = make_char4(
            (char)__float2int_rn((v.x - a0 * step) * inv2),
            (char)__float2int_rn((v.y - a1 * step) * inv2),
            (char)__float2int_rn((v.z - a2 * step) * inv2),
            (char)__float2int_rn((v.w - a3 * step) * inv2));
        ((char4*)(g_x1 + (size_t)n * HDIM))[i] = c1;
        ((char4*)(g_x2 + (size_t)n * HDIM))[i] = c2;
    }
}

// row-quantize a2f [N,F] using precomputed steps g_sa2
__global__ void __launch_bounds__(256) quant_a2_kernel()
{
    int n = blockIdx.x;
    const float* ar = g_a2f + (size_t)n * FDIM;
    float step = g_sa2[n];
    float inv1 = 1.f / step, inv2 = 254.f / step;
    for (int i = threadIdx.x; i < FDIM / 4; i += 256) {
        float4 v = ((const float4*)ar)[i];
        int a0 = __float2int_rn(v.x * inv1), a1 = __float2int_rn(v.y * inv1);
        int a2 = __float2int_rn(v.z * inv1), a3 = __float2int_rn(v.w * inv1);
        char4 c1 = make_char4((char)a0, (char)a1, (char)a2, (char)a3);
        char4 c2 = make_char4(
            (char)__float2int_rn((v.x - a0 * step) * inv2),
            (char)__float2int_rn((v.y - a1 * step) * inv2),
            (char)__float2int_rn((v.z - a2 * step) * inv2),
            (char)__float2int_rn((v.w - a3 * step) * inv2));
        ((char4*)(g_aq1 + (size_t)n * FDIM))[i] = c1;
        ((char4*)(g_aq2 + (size_t)n * FDIM))[i] = c2;
    }
}

// ---------------------------------------------------------------------------
// Router + LoRA coefficients (unchanged; passing since round 1)
// ---------------------------------------------------------------------------
__global__ void __launch_bounds__(128) router_lora_kernel(
    const float* __restrict__ x, const float* __restrict__ router_w,
    const float* __restrict__ lora_A, float* __restrict__ logits_out)
{
    int n = blockIdx.x;
    __shared__ float xs[HDIM];
    __shared__ float logits[NEXP];
    __shared__ int   sel[2];
    __shared__ float rws[2];

    const float* xr = x + (size_t)n * HDIM;
    for (int i = threadIdx.x; i < HDIM / 4; i += blockDim.x)
        ((float4*)xs)[i] = ((const float4*)xr)[i];
    __syncthreads();

    int wid = threadIdx.x >> 5, lane = threadIdx.x & 31;
    for (int e = wid; e < NEXP; e += 4) {
        const float* wr = router_w + (size_t)e * HDIM;
        float s = 0.f;
        for (int h = lane; h < HDIM; h += 32) s += xs[h] * wr[h];
        #pragma unroll
        for (int o = 16; o; o >>= 1) s += __shfl_down_sync(0xffffffffu, s, o);
        if (lane == 0) {
            logits[e] = s;
            if (logits_out) logits_out[(size_t)n * NEXP + e] = s;
        }
    }
    __syncthreads();

    if (threadIdx.x == 0) {
        float m = -1e30f;
        for (int e = 0; e < NEXP; e++) m = fmaxf(m, logits[e]);
        float p[NEXP];
        for (int e = 0; e < NEXP; e++) p[e] = expf(logits[e] - m);
        int i0 = 0;
        for (int e = 1; e < NEXP; e++) if (p[e] > p[i0]) i0 = e;
        int i1 = -1;
        for (int e = 0; e < NEXP; e++) {
            if (e == i0) continue;
            if (i1 < 0 || p[e] > p[i1]) i1 = e;
        }
        float s2 = p[i0] + p[i1];
        sel[0] = i0; sel[1] = i1;
        rws[0] = p[i0] / s2; rws[1] = p[i1] / s2;
    }
    if (threadIdx.x < NEXP * NR) g_c[n * NEXP * NR + threadIdx.x] = 0.f;
    __syncthreads();

    int p  = threadIdx.x >> 3;
    int l8 = threadIdx.x & 7;
    int k  = p >> 3;
    int r  = p & 7;
    int e  = sel[k];
    const float* A = lora_A + (size_t)e * HDIM * NR + r;
    float s = 0.f;
    for (int h = l8; h < HDIM; h += 8) s += xs[h] * A[(size_t)h * NR];
    s += __shfl_down_sync(0xffffffffu, s, 4);
    s += __shfl_down_sync(0xffffffffu, s, 2);
    s += __shfl_down_sync(0xffffffffu, s, 1);
    if (l8 == 0) g_c[n * NEXP * NR + e * NR + r] = rws[k] * LSCALE * s;
}

// ---------------------------------------------------------------------------
// Small fp32 SGEMM for LoRA (K=64), writes out with beta=0
// ---------------------------------------------------------------------------
__global__ void __launch_bounds__(256) sgemm128_kernel(
    const float* __restrict__ A, const float* __restrict__ B,
    float* __restrict__ C, int M, int N, int K)
{
    __shared__ float As[8][128];
    __shared__ float Bs[8][128];
    int tid = threadIdx.x;
    int m0 = blockIdx.y * 128, n0 = blockIdx.x * 128;
    int aRow = tid >> 1, aCol = (tid & 1) * 4;
    int bRow = tid >> 5, bCol = (tid & 31) * 4;
    const float* Aptr = A + (size_t)(m0 + aRow) * K + aCol;
    const float* Bptr = B + (size_t)bRow * N + n0 + bCol;
    int ty = tid >> 4, tx = tid & 15;

    float acc[8][8];
    #pragma unroll
    for (int i = 0; i < 8; i++)
        #pragma unroll
        for (int j = 0; j < 8; j++) acc[i][j] = 0.f;

    for (int k0 = 0; k0 < K; k0 += 8) {
        float4 av = *(const float4*)Aptr; Aptr += 8;
        float4 bv = *(const float4*)Bptr; Bptr += (size_t)8 * N;
        As[aCol + 0][aRow] = av.x; As[aCol + 1][aRow] = av.y;
        As[aCol + 2][aRow] = av.z; As[aCol + 3][aRow] = av.w;
        *(float4*)&Bs[bRow][bCol] = bv;
        __syncthreads();
        #pragma unroll
        for (int kk = 0; kk < 8; kk++) {
            float a[8], b[8];
            *(float4*)(a)     = *(const float4*)&As[kk][ty * 8];
            *(float4*)(a + 4) = *(const float4*)&As[kk][ty * 8 + 4];
            *(float4*)(b)     = *(const float4*)&Bs[kk][tx * 8];
            *(float4*)(b + 4) = *(const float4*)&Bs[kk][tx * 8 + 4];
            #pragma unroll
            for (int i = 0; i < 8; i++)
                #pragma unroll
                for (int j = 0; j < 8; j++)
                    acc[i][j] = fmaf(a[i], b[j], acc[i][j]);
        }
        __syncthreads();
    }
    #pragma unroll
    for (int i = 0; i < 8; i++) {
        float* Cr = C + (size_t)(m0 + ty * 8 + i) * N + n0 + tx * 8;
        *(float4*)Cr       = make_float4(acc[i][0], acc[i][1], acc[i][2], acc[i][3]);
        *(float4*)(Cr + 4) = make_float4(acc[i][4], acc[i][5], acc[i][6], acc[i][7]);
    }
}

// ---------------------------------------------------------------------------
// int8 two-slice GEMM via mma.sync.m16n8k32.s8:
//   D = stepA[i]*stepB[j]*(P1 + P2/254),  P1 = A1B1, P2 = A1B2 + A2B1
// A [M,K], B [N,K] int8 K-major. CTA 128x128, K-chunk 128, 3 stages.
// mode 0: C  = D
// mode 1: v = silu(gate)*D; write v to a2f; track per-row max -> g_sa2 (atomic)
// mode 2: C += D
// ---------------------------------------------------------------------------
#define STAGE_BYTES 65536
#define GEMM_SMEM   (3 * STAGE_BYTES)

__device__ __forceinline__ void issue_stage_i8(
    uint32_t st, const int8_t* A1, const int8_t* A2,
    const int8_t* B1, const int8_t* B2,
    int m0, int n0, int kpos, int K, int lr, int lkc)
{
    #pragma unroll
    for (int rr = 0; rr < 128; rr += 32) {
        int row = lr + rr;
        uint32_t so = row * 128 + ((lkc ^ (row & 7)) << 4);
        size_t ga = (size_t)(m0 + row) * K + kpos + lkc * 16;
        size_t gb = (size_t)(n0 + row) * K + kpos + lkc * 16;
        CP16(st + so,         A1 + ga);
        CP16(st + 16384 + so, A2 + ga);
        CP16(st + 32768 + so, B1 + gb);
        CP16(st + 49152 + so, B2 + gb);
    }
    CP_COMMIT();
}

__global__ void __launch_bounds__(256, 1) gemm_i8_kernel(
    const int8_t* __restrict__ A1, const int8_t* __restrict__ A2,
    const int8_t* __restrict__ B1, const int8_t* __restrict__ B2,
    const float* __restrict__ stepA, const float* __restrict__ stepB,
    float* __restrict__ C, const float* __restrict__ gate,
    float* __restrict__ a2f, int K, int mode)
{
    extern __shared__ __align__(1024) char smem[];
    uint32_t sb = smem_u32(smem);
    int tid = threadIdx.x;
    int wid = tid >> 5, lane = tid & 31;
    int wm = wid >> 2, wn = wid & 3;          // 2x4 warps, warp tile 64m x 32n
    int m0 = blockIdx.y * 128, n0 = blockIdx.x * 128;
    int NT = K >> 7;

    int lr = tid >> 3, lkc = tid & 7;

    int laneM  = lane & 15;
    int kHalfA = lane >> 4;
    int aSw    = laneM & 7;
    uint32_t rowOffA[4];
    #pragma unroll
    for (int tm = 0; tm < 4; tm++)
        rowOffA[tm] = (uint32_t)(wm * 64 + tm * 16 + laneM) * 128;
    int l7     = lane & 7;
    int kHalfB = (lane >> 3) & 1;
    uint32_t rowOffB[2];
    #pragma unroll
    for (int pr = 0; pr < 2; pr++)
        rowOffB[pr] = (uint32_t)(wn * 32 + pr * 16 + ((lane >> 4) & 1) * 8 + l7) * 128;

    int acc1[4][4][4], acc2[4][4][4];
    #pragma unroll
    for (int i = 0; i < 4; i++)
        #pragma unroll
        for (int j = 0; j < 4; j++)
            #pragma unroll
            for (int q = 0; q < 4; q++) { acc1[i][j][q] = 0; acc2[i][j][q] = 0; }

    issue_stage_i8(sb,               A1, A2, B1, B2, m0, n0, 0,   K, lr, lkc);
    issue_stage_i8(sb + STAGE_BYTES, A1, A2, B1, B2, m0, n0, 128, K, lr, lkc);

    for (int kt = 0; kt < NT; kt++) {
        CP_WAIT1();
        __syncthreads();
        if (kt + 2 < NT)
            issue_stage_i8(sb + ((kt + 2) % 3) * STAGE_BYTES, A1, A2, B1, B2,
                           m0, n0, (kt + 2) << 7, K, lr, lkc);
        else
            CP_COMMIT();

        uint32_t st = sb + (kt % 3) * STAGE_BYTES;
        #pragma unroll
        for (int ks = 0; ks < 4; ks++) {
            uint32_t ah[4][4], al[4][4], bh[8], bl[8];
            uint32_t chA = (uint32_t)(((ks * 2 + kHalfA) ^ aSw) << 4);
            #pragma unroll
            for (int tm = 0; tm < 4; tm++) {
                LDSM4(ah[tm][0], ah[tm][1], ah[tm][2], ah[tm][3], st + rowOffA[tm] + chA);
                LDSM4(al[tm][0], al[tm][1], al[tm][2], al[tm][3], st + 16384 + rowOffA[tm] + chA);
            }
            uint32_t chB = (uint32_t)(((ks * 2 + kHalfB) ^ l7) << 4);
            LDSM4(bh[0], bh[1], bh[2], bh[3], st + 32768 + rowOffB[0] + chB);
            LDSM4(bh[4], bh[5], bh[6], bh[7], st + 32768 + rowOffB[1] + chB);
            LDSM4(bl[0], bl[1], bl[2], bl[3], st + 49152 + rowOffB[0] + chB);
            LDSM4(bl[4], bl[5], bl[6], bl[7], st + 49152 + rowOffB[1] + chB);
            #pragma unroll
            for (int tm = 0; tm < 4; tm++)
                #pragma unroll
                for (int tn = 0; tn < 4; tn++) {
                    MMA_S8(acc1[tm][tn], ah[tm][0], ah[tm][1], ah[tm][2], ah[tm][3],
                           bh[2 * tn], bh[2 * tn + 1]);
                    MMA_S8(acc2[tm][tn], ah[tm][0], ah[tm][1], ah[tm][2], ah[tm][3],
                           bl[2 * tn], bl[2 * tn + 1]);
                    MMA_S8(acc2[tm][tn], al[tm][0], al[tm][1], al[tm][2], al[tm][3],
                           bh[2 * tn], bh[2 * tn + 1]);
                }
        }
    }

    // epilogue
    int g2 = lane >> 2, q2 = (lane & 3) * 2;
    size_t Nt = (size_t)gridDim.x * 128;
    #pragma unroll
    for (int tm = 0; tm < 4; tm++) {
        int mg0 = m0 + wm * 64 + tm * 16 + g2;
        float sA0 = stepA[mg0], sA1 = stepA[mg0 + 8];
        float rm0 = 0.f, rm1 = 0.f;
        #pragma unroll
        for (int tn = 0; tn < 4; tn++) {
            int cg = n0 + wn * 32 + tn * 8 + q2;
            float sB0 = stepB[cg], sB1 = stepB[cg + 1];
            int* p1 = acc1[tm][tn];
            int* p2 = acc2[tm][tn];
            float d0 = sA0 * sB0 * ((float)p1[0] + (float)p2[0] * (1.f / 254.f));
            float d1 = sA0 * sB1 * ((float)p1[1] + (float)p2[1] * (1.f / 254.f));
            float d2 = sA1 * sB0 * ((float)p1[2] + (float)p2[2] * (1.f / 254.f));
            float d3 = sA1 * sB1 * ((float)p1[3] + (float)p2[3] * (1.f / 254.f));
            size_t o0 = (size_t)mg0 * Nt + cg;
            size_t o1 = o0 + 8 * Nt;
            if (mode == 0) {
                *(float2*)(C + o0) = make_float2(d0, d1);
                *(float2*)(C + o1) = make_float2(d2, d3);
            } else if (mode == 1) {
                float2 ga0 = *(const float2*)(gate + o0);
                float2 ga1 = *(const float2*)(gate + o1);
                float v0 = ga0.x / (1.f + __expf(-ga0.x)) * d0;
                float v1 = ga0.y / (1.f + __expf(-ga0.y)) * d1;
                float v2 = ga1.x / (1.f + __expf(-ga1.x)) * d2;
                float v3 = ga1.y / (1.f + __expf(-ga1.y)) * d3;
                *(float2*)(a2f + o0) = make_float2(v0, v1);
                *(float2*)(a2f + o1) = make_float2(v2, v3);
                rm0 = fmaxf(rm0, fmaxf(fabsf(v0), fabsf(v1)));
                rm1 = fmaxf(rm1, fmaxf(fabsf(v2), fabsf(v3)));
            } else {
                float2 c0 = *(const float2*)(C + o0);
                float2 c1 = *(const float2*)(C + o1);
                c0.x += d0; c0.y += d1;
                c1.x += d2; c1.y += d3;
                *(float2*)(C + o0) = c0;
                *(float2*)(C + o1) = c1;
            }
        }
        if (mode == 1) {
            // reduce the 4 lanes sharing a row, then one atomic per row
            rm0 = fmaxf(rm0, __shfl_xor_sync(0xffffffffu, rm0, 1));
            rm0 = fmaxf(rm0, __shfl_xor_sync(0xffffffffu, rm0, 2));
            rm1 = fmaxf(rm1, __shfl_xor_sync(0xffffffffu, rm1, 1));
            rm1 = fmaxf(rm1, __shfl_xor_sync(0xffffffffu, rm1, 2));
            if ((lane & 3) == 0) {
                atomicMax((unsigned int*)&g_sa2[mg0],     __float_as_uint(rm0));
                atomicMax((unsigned int*)&g_sa2[mg0 + 8], __float_as_uint(rm1));
            }
        }
    }
}

// ---------------------------------------------------------------------------
extern "C" void kernel_launch(void* const* d_in, const int* in_sizes, int n_in,
                              void* d_out, int out_size)
{
    const float* x        = (const float*)d_in[0];
    const float* router_w = (const float*)d_in[1];
    const float* w1       = (const float*)d_in[2];
    const float* w2       = (const float*)d_in[3];
    const float* w3       = (const float*)d_in[4];
    const float* lora_A   = (const float*)d_in[5];
    const float* lora_B   = (const float*)d_in[6];
    float* out = (float*)d_out;

    static bool init_done = false;
    static float *h1, *a2f, *cc, *sb1, *sb3, *sb2, *sax, *sa2;
    static int8_t *x1, *x2, *b1q1, *b1q2, *b3q1, *b3q2, *b2q1, *b2q2, *aq1, *aq2;
    if (!init_done) {
        cudaGetSymbolAddress((void**)&h1,   g_h1);
        cudaGetSymbolAddress((void**)&a2f,  g_a2f);
        cudaGetSymbolAddress((void**)&cc,   g_c);
        cudaGetSymbolAddress((void**)&sb1,  g_sb1);
        cudaGetSymbolAddress((void**)&sb3,  g_sb3);
        cudaGetSymbolAddress((void**)&sb2,  g_sb2);
        cudaGetSymbolAddress((void**)&sax,  g_sax);
        cudaGetSymbolAddress((void**)&sa2,  g_sa2);
        cudaGetSymbolAddress((void**)&x1,   g_x1);
        cudaGetSymbolAddress((void**)&x2,   g_x2);
        cudaGetSymbolAddress((void**)&b1q1, g_b1q1);
        cudaGetSymbolAddress((void**)&b1q2, g_b1q2);
        cudaGetSymbolAddress((void**)&b3q1, g_b3q1);
        cudaGetSymbolAddress((void**)&b3q2, g_b3q2);
        cudaGetSymbolAddress((void**)&b2q1, g_b2q1);
        cudaGetSymbolAddress((void**)&b2q2, g_b2q2);
        cudaGetSymbolAddress((void**)&aq1,  g_aq1);
        cudaGetSymbolAddress((void**)&aq2,  g_aq2);
        cudaFuncSetAttribute(gemm_i8_kernel,
                             cudaFuncAttributeMaxDynamicSharedMemorySize, GEMM_SMEM);
        init_done = true;
    }

    float* logits_out = nullptr;
    if ((size_t)out_size >= (size_t)NTOK * HDIM + (size_t)NTOK * NEXP)
        logits_out = out + (size_t)NTOK * HDIM;

    // --- weight scale + quantization (re-done each call; deterministic) ---
    zero_kernel<<<(FDIM + 255) / 256, 256>>>(sb1, FDIM);
    zero_kernel<<<(FDIM + 255) / 256, 256>>>(sb3, FDIM);
    zero_kernel<<<(HDIM + 255) / 256, 256>>>(sb2, HDIM);
    zero_kernel<<<(NTOK + 255) / 256, 256>>>(sa2, NTOK);

    colmax_kernel<<<dim3(FDIM / 256, HDIM / 512), 256>>>(w1, sb1, HDIM, FDIM);
    colmax_kernel<<<dim3(FDIM / 256, HDIM / 512), 256>>>(w3, sb3, HDIM, FDIM);
    colmax_kernel<<<dim3(HDIM / 256, FDIM / 512), 256>>>(w2, sb2, FDIM, HDIM);

    finalize_scale_kernel<<<(FDIM + 255) / 256, 256>>>(sb1, FDIM);
    finalize_scale_kernel<<<(FDIM + 255) / 256, 256>>>(sb3, FDIM);
    finalize_scale_kernel<<<(HDIM + 255) / 256, 256>>>(sb2, HDIM);

    transpose_quant_kernel<<<dim3(FDIM / 32, HDIM / 32), 256>>>(w1, b1q1, b1q2, sb1, HDIM, FDIM);
    transpose_quant_kernel<<<dim3(FDIM / 32, HDIM / 32), 256>>>(w3, b3q1, b3q2, sb3, HDIM, FDIM);
    transpose_quant_kernel<<<dim3(HDIM / 32, FDIM / 32), 256>>>(w2, b2q1, b2q2, sb2, FDIM, HDIM);

    quant_x_kernel<<<NTOK, 256>>>(x);

    // --- router + LoRA; LoRA GEMM initializes out (beta=0) ---
    router_lora_kernel<<<NTOK, 128>>>(x, router_w, lora_A, logits_out);
    sgemm128_kernel<<<dim3(HDIM / 128, NTOK / 128), 256>>>(cc, lora_B, out, NTOK, HDIM, NEXP * NR);

    // --- GEMM1: h1 = x @ w1 ---
    gemm_i8_kernel<<<dim3(FDIM / 128, NTOK / 128), 256, GEMM_SMEM>>>(
        x1, x2, b1q1, b1q2, sax, sb1, h1, nullptr, nullptr, HDIM, 0);

    // --- GEMM3 (+silu fuse): a2f = silu(h1) * (x @ w3); rowmax -> sa2 ---
    gemm_i8_kernel<<<dim3(FDIM / 128, NTOK / 128), 256, GEMM_SMEM>>>(
        x1, x2, b3q1, b3q2, sax, sb3, nullptr, h1, a2f, HDIM, 1);

    finalize_scale_kernel<<<(NTOK + 255) / 256, 256>>>(sa2, NTOK);
    quant_a2_kernel<<<NTOK, 256>>>();

    // --- GEMM2: out += a2 @ w2 ---
    gemm_i8_kernel<<<dim3(HDIM / 128, NTOK / 128), 256, GEMM_SMEM>>>(
        aq1, aq2, b2q1, b2q2, sa2, sb2, out, nullptr, nullptr, FDIM, 2);
}

// round 5
// speedup vs baseline: 7.7962x; 7.7962x over previous
#include <cuda_runtime.h>
#include <cuda_fp16.h>
#include <cstdint>
#include <math.h>

#define NTOK 4096
#define HDIM 4096
#define FDIM 14336
#define NEXP 8
#define NR   8
#define LSCALE 2.0f

// ---------------------------------------------------------------------------
// Scratch (__device__ globals; allocation-free rule)
// ---------------------------------------------------------------------------
__device__ __half g_xh[(size_t)NTOK * HDIM];   // x as fp16 [N,H]
__device__ __half g_b1[(size_t)FDIM * HDIM];   // w1^T [F,H] fp16
__device__ __half g_b3[(size_t)FDIM * HDIM];   // w3^T [F,H] fp16
__device__ __half g_b2[(size_t)HDIM * FDIM];   // w2^T [H,F] fp16
__device__ __half g_a2[(size_t)NTOK * FDIM];   // silu(h1)*h3 fp16 [N,F]
__device__ float  g_h1[(size_t)NTOK * FDIM];   // x@w1 gate (fp32)
__device__ float  g_c[NTOK * NEXP * NR];       // LoRA coefficients

// ---------------------------------------------------------------------------
// Asm helpers (sm_80-level features; legal on plain sm_103 target)
// ---------------------------------------------------------------------------
__device__ __forceinline__ uint32_t smem_u32(const void* p) {
    uint32_t a;
    asm("{ .reg .u64 t; cvta.to.shared.u64 t, %1; cvt.u32.u64 %0, t; }" : "=r"(a) : "l"(p));
    return a;
}

#define CP16(dst, src) \
    asm volatile("cp.async.cg.shared.global [%0], [%1], 16;" :: "r"(dst), "l"(src))
#define CP_COMMIT() asm volatile("cp.async.commit_group;" ::: "memory")
#define CP_WAIT1()  asm volatile("cp.async.wait_group 1;" ::: "memory")

#define LDSM4(r0, r1, r2, r3, a) \
    asm volatile("ldmatrix.sync.aligned.m8n8.x4.shared.b16 {%0,%1,%2,%3}, [%4];" \
        : "=r"(r0), "=r"(r1), "=r"(r2), "=r"(r3) : "r"(a))

#define MMA_F16(c, a0, a1, a2, a3, b0, b1) \
    asm volatile("mma.sync.aligned.m16n8k16.row.col.f32.f16.f16.f32 " \
        "{%0,%1,%2,%3}, {%4,%5,%6,%7}, {%8,%9}, {%0,%1,%2,%3};" \
        : "+f"((c)[0]), "+f"((c)[1]), "+f"((c)[2]), "+f"((c)[3]) \
        : "r"(a0), "r"(a1), "r"(a2), "r"(a3), "r"(b0), "r"(b1))

// ---------------------------------------------------------------------------
// Conversion kernels
// ---------------------------------------------------------------------------
__global__ void __launch_bounds__(256) convert_x_kernel(const float* __restrict__ x) {
    size_t n = (size_t)NTOK * HDIM;
    size_t stride = (size_t)gridDim.x * blockDim.x * 4;
    for (size_t i = ((size_t)blockIdx.x * blockDim.x + threadIdx.x) * 4; i < n; i += stride) {
        float4 v = *(const float4*)(x + i);
        __half2 h0 = __floats2half2_rn(v.x, v.y);
        __half2 h1 = __floats2half2_rn(v.z, v.w);
        *(__half2*)(g_xh + i)     = h0;
        *(__half2*)(g_xh + i + 2) = h1;
    }
}

// W [K,N] fp32 -> [N,K] fp16 (transpose + convert)
__global__ void __launch_bounds__(256) transpose_convert_kernel(
    const float* __restrict__ W, __half* __restrict__ out, int K, int N)
{
    __shared__ float t[32][33];
    int n0 = blockIdx.x * 32, k0 = blockIdx.y * 32;
    int tx = threadIdx.x & 31, ty = threadIdx.x >> 5;   // 32 x 8
    #pragma unroll
    for (int j = 0; j < 4; j++)
        t[ty + 8 * j][tx] = W[(size_t)(k0 + ty + 8 * j) * N + n0 + tx];
    __syncthreads();
    #pragma unroll
    for (int j = 0; j < 4; j++) {
        int r = ty + 8 * j;
        out[(size_t)(n0 + r) * K + k0 + tx] = __float2half_rn(t[tx][r]);
    }
}

// ---------------------------------------------------------------------------
// Router + LoRA coefficients (unchanged; passing since round 1)
// ---------------------------------------------------------------------------
__global__ void __launch_bounds__(128) router_lora_kernel(
    const float* __restrict__ x, const float* __restrict__ router_w,
    const float* __restrict__ lora_A, float* __restrict__ logits_out)
{
    int n = blockIdx.x;
    __shared__ float xs[HDIM];
    __shared__ float logits[NEXP];
    __shared__ int   sel[2];
    __shared__ float rws[2];

    const float* xr = x + (size_t)n * HDIM;
    for (int i = threadIdx.x; i < HDIM / 4; i += blockDim.x)
        ((float4*)xs)[i] = ((const float4*)xr)[i];
    __syncthreads();

    int wid = threadIdx.x >> 5, lane = threadIdx.x & 31;
    for (int e = wid; e < NEXP; e += 4) {
        const float* wr = router_w + (size_t)e * HDIM;
        float s = 0.f;
        for (int h = lane; h < HDIM; h += 32) s += xs[h] * wr[h];
        #pragma unroll
        for (int o = 16; o; o >>= 1) s += __shfl_down_sync(0xffffffffu, s, o);
        if (lane == 0) {
            logits[e] = s;
            if (logits_out) logits_out[(size_t)n * NEXP + e] = s;
        }
    }
    __syncthreads();

    if (threadIdx.x == 0) {
        float m = -1e30f;
        for (int e = 0; e < NEXP; e++) m = fmaxf(m, logits[e]);
        float p[NEXP];
        for (int e = 0; e < NEXP; e++) p[e] = expf(logits[e] - m);
        int i0 = 0;
        for (int e = 1; e < NEXP; e++) if (p[e] > p[i0]) i0 = e;
        int i1 = -1;
        for (int e = 0; e < NEXP; e++) {
            if (e == i0) continue;
            if (i1 < 0 || p[e] > p[i1]) i1 = e;
        }
        float s2 = p[i0] + p[i1];
        sel[0] = i0; sel[1] = i1;
        rws[0] = p[i0] / s2; rws[1] = p[i1] / s2;
    }
    if (threadIdx.x < NEXP * NR) g_c[n * NEXP * NR + threadIdx.x] = 0.f;
    __syncthreads();

    int p  = threadIdx.x >> 3;
    int l8 = threadIdx.x & 7;
    int k  = p >> 3;
    int r  = p & 7;
    int e  = sel[k];
    const float* A = lora_A + (size_t)e * HDIM * NR + r;
    float s = 0.f;
    for (int h = l8; h < HDIM; h += 8) s += xs[h] * A[(size_t)h * NR];
    s += __shfl_down_sync(0xffffffffu, s, 4);
    s += __shfl_down_sync(0xffffffffu, s, 2);
    s += __shfl_down_sync(0xffffffffu, s, 1);
    if (l8 == 0) g_c[n * NEXP * NR + e * NR + r] = rws[k] * LSCALE * s;
}

// ---------------------------------------------------------------------------
// Small fp32 SGEMM for LoRA (K=64), writes out with beta=0
// ---------------------------------------------------------------------------
__global__ void __launch_bounds__(256) sgemm128_kernel(
    const float* __restrict__ A, const float* __restrict__ B,
    float* __restrict__ C, int M, int N, int K)
{
    __shared__ float As[8][128];
    __shared__ float Bs[8][128];
    int tid = threadIdx.x;
    int m0 = blockIdx.y * 128, n0 = blockIdx.x * 128;
    int aRow = tid >> 1, aCol = (tid & 1) * 4;
    int bRow = tid >> 5, bCol = (tid & 31) * 4;
    const float* Aptr = A + (size_t)(m0 + aRow) * K + aCol;
    const float* Bptr = B + (size_t)bRow * N + n0 + bCol;
    int ty = tid >> 4, tx = tid & 15;

    float acc[8][8];
    #pragma unroll
    for (int i = 0; i < 8; i++)
        #pragma unroll
        for (int j = 0; j < 8; j++) acc[i][j] = 0.f;

    for (int k0 = 0; k0 < K; k0 += 8) {
        float4 av = *(const float4*)Aptr; Aptr += 8;
        float4 bv = *(const float4*)Bptr; Bptr += (size_t)8 * N;
        As[aCol + 0][aRow] = av.x; As[aCol + 1][aRow] = av.y;
        As[aCol + 2][aRow] = av.z; As[aCol + 3][aRow] = av.w;
        *(float4*)&Bs[bRow][bCol] = bv;
        __syncthreads();
        #pragma unroll
        for (int kk = 0; kk < 8; kk++) {
            float a[8], b[8];
            *(float4*)(a)     = *(const float4*)&As[kk][ty * 8];
            *(float4*)(a + 4) = *(const float4*)&As[kk][ty * 8 + 4];
            *(float4*)(b)     = *(const float4*)&Bs[kk][tx * 8];
            *(float4*)(b + 4) = *(const float4*)&Bs[kk][tx * 8 + 4];
            #pragma unroll
            for (int i = 0; i < 8; i++)
                #pragma unroll
                for (int j = 0; j < 8; j++)
                    acc[i][j] = fmaf(a[i], b[j], acc[i][j]);
        }
        __syncthreads();
    }
    #pragma unroll
    for (int i = 0; i < 8; i++) {
        float* Cr = C + (size_t)(m0 + ty * 8 + i) * N + n0 + tx * 8;
        *(float4*)Cr       = make_float4(acc[i][0], acc[i][1], acc[i][2], acc[i][3]);
        *(float4*)(Cr + 4) = make_float4(acc[i][4], acc[i][5], acc[i][6], acc[i][7]);
    }
}

// ---------------------------------------------------------------------------
// Single-pass fp16 GEMM via mma.sync.m16n8k16: D = A @ B^T (fp32 accum)
// A [M,K], B [N,K] fp16 K-major. CTA 128x128, K-chunk 64, 3 stages (32KB each).
// mode 0: C  = D               (gate: h1)
// mode 1: a2 = silu(gate)*D    (fp16 out)
// mode 2: C += D               (down-proj accumulate onto out)
// ---------------------------------------------------------------------------
#define STAGE_BYTES 32768
#define GEMM_SMEM   (3 * STAGE_BYTES)

__device__ __forceinline__ void issue_stage_f16(
    uint32_t st, const __half* A, const __half* B,
    int m0, int n0, int kpos, int K, int lr, int lkc)
{
    #pragma unroll
    for (int rr = 0; rr < 128; rr += 32) {
        int row = lr + rr;
        uint32_t so = row * 128 + ((lkc ^ (row & 7)) << 4);
        size_t ga = (size_t)(m0 + row) * K + kpos + lkc * 8;
        size_t gb = (size_t)(n0 + row) * K + kpos + lkc * 8;
        CP16(st + so,         A + ga);
        CP16(st + 16384 + so, B + gb);
    }
    CP_COMMIT();
}

__global__ void __launch_bounds__(256, 2) gemm_f16_kernel(
    const __half* __restrict__ A, const __half* __restrict__ B,
    float* __restrict__ C, const float* __restrict__ gate,
    __half* __restrict__ oA2, int K, int mode)
{
    extern __shared__ __align__(1024) char smem[];
    uint32_t sb = smem_u32(smem);
    int tid = threadIdx.x;
    int wid = tid >> 5, lane = tid & 31;
    int wm = wid >> 2, wn = wid & 3;          // 2x4 warps, warp tile 64m x 32n
    int m0 = blockIdx.y * 128, n0 = blockIdx.x * 128;
    int NT = K >> 6;

    int lr = tid >> 3, lkc = tid & 7;

    int laneM  = lane & 15;
    int kHalfA = lane >> 4;
    int aSw    = laneM & 7;
    uint32_t rowOffA[4];
    #pragma unroll
    for (int tm = 0; tm < 4; tm++)
        rowOffA[tm] = (uint32_t)(wm * 64 + tm * 16 + laneM) * 128;
    int l7     = lane & 7;
    int kHalfB = (lane >> 3) & 1;
    uint32_t rowOffB[2];
    #pragma unroll
    for (int pr = 0; pr < 2; pr++)
        rowOffB[pr] = (uint32_t)(wn * 32 + pr * 16 + ((lane >> 4) & 1) * 8 + l7) * 128;

    float acc[4][4][4];
    #pragma unroll
    for (int i = 0; i < 4; i++)
        #pragma unroll
        for (int j = 0; j < 4; j++)
            #pragma unroll
            for (int q = 0; q < 4; q++) acc[i][j][q] = 0.f;

    issue_stage_f16(sb,               A, B, m0, n0, 0,  K, lr, lkc);
    issue_stage_f16(sb + STAGE_BYTES, A, B, m0, n0, 64, K, lr, lkc);

    for (int kt = 0; kt < NT; kt++) {
        CP_WAIT1();
        __syncthreads();
        if (kt + 2 < NT)
            issue_stage_f16(sb + ((kt + 2) % 3) * STAGE_BYTES, A, B,
                            m0, n0, (kt + 2) << 6, K, lr, lkc);
        else
            CP_COMMIT();  // keep committed-count = kt+2 so WAIT1 retires stage kt

        uint32_t st = sb + (kt % 3) * STAGE_BYTES;
        #pragma unroll
        for (int kk = 0; kk < 4; kk++) {
            uint32_t ah[4][4], bh[8];
            uint32_t chA = (uint32_t)(((kk * 2 + kHalfA) ^ aSw) << 4);
            #pragma unroll
            for (int tm = 0; tm < 4; tm++)
                LDSM4(ah[tm][0], ah[tm][1], ah[tm][2], ah[tm][3], st + rowOffA[tm] + chA);
            uint32_t chB = (uint32_t)(((kk * 2 + kHalfB) ^ l7) << 4);
            LDSM4(bh[0], bh[1], bh[2], bh[3], st + 16384 + rowOffB[0] + chB);
            LDSM4(bh[4], bh[5], bh[6], bh[7], st + 16384 + rowOffB[1] + chB);
            #pragma unroll
            for (int tm = 0; tm < 4; tm++)
                #pragma unroll
                for (int tn = 0; tn < 4; tn++)
                    MMA_F16(acc[tm][tn], ah[tm][0], ah[tm][1], ah[tm][2], ah[tm][3],
                            bh[2 * tn], bh[2 * tn + 1]);
        }
    }

    // epilogue
    int g2 = lane >> 2, q2 = (lane & 3) * 2;
    size_t Nt = (size_t)gridDim.x * 128;
    #pragma unroll
    for (int tm = 0; tm < 4; tm++) {
        #pragma unroll
        for (int tn = 0; tn < 4; tn++) {
            int mg = m0 + wm * 64 + tm * 16 + g2;
            int cg = n0 + wn * 32 + tn * 8 + q2;
            size_t o0 = (size_t)mg * Nt + cg;
            size_t o1 = o0 + 8 * Nt;
            float* a = acc[tm][tn];
            if (mode == 0) {
                *(float2*)(C + o0) = make_float2(a[0], a[1]);
                *(float2*)(C + o1) = make_float2(a[2], a[3]);
            } else if (mode == 1) {
                float2 ga0 = *(const float2*)(gate + o0);
                float2 ga1 = *(const float2*)(gate + o1);
                float v0 = ga0.x / (1.f + __expf(-ga0.x)) * a[0];
                float v1 = ga0.y / (1.f + __expf(-ga0.y)) * a[1];
                float v2 = ga1.x / (1.f + __expf(-ga1.x)) * a[2];
                float v3 = ga1.y / (1.f + __expf(-ga1.y)) * a[3];
                *(__half2*)(oA2 + o0) = __floats2half2_rn(v0, v1);
                *(__half2*)(oA2 + o1) = __floats2half2_rn(v2, v3);
            } else {
                float2 c0 = *(const float2*)(C + o0);
                float2 c1 = *(const float2*)(C + o1);
                c0.x += a[0]; c0.y += a[1];
                c1.x += a[2]; c1.y += a[3];
                *(float2*)(C + o0) = c0;
                *(float2*)(C + o1) = c1;
            }
        }
    }
}

// ---------------------------------------------------------------------------
extern "C" void kernel_launch(void* const* d_in, const int* in_sizes, int n_in,
                              void* d_out, int out_size)
{
    const float* x        = (const float*)d_in[0];
    const float* router_w = (const float*)d_in[1];
    const float* w1       = (const float*)d_in[2];
    const float* w2       = (const float*)d_in[3];
    const float* w3       = (const float*)d_in[4];
    const float* lora_A   = (const float*)d_in[5];
    const float* lora_B   = (const float*)d_in[6];
    float* out = (float*)d_out;

    static bool init_done = false;
    static float *h1, *cc;
    static __half *xh, *b1, *b3, *b2, *a2;
    if (!init_done) {
        cudaGetSymbolAddress((void**)&h1, g_h1);
        cudaGetSymbolAddress((void**)&cc, g_c);
        cudaGetSymbolAddress((void**)&xh, g_xh);
        cudaGetSymbolAddress((void**)&b1, g_b1);
        cudaGetSymbolAddress((void**)&b3, g_b3);
        cudaGetSymbolAddress((void**)&b2, g_b2);
        cudaGetSymbolAddress((void**)&a2, g_a2);
        cudaFuncSetAttribute(gemm_f16_kernel,
                             cudaFuncAttributeMaxDynamicSharedMemorySize, GEMM_SMEM);
        init_done = true;
    }

    float* logits_out = nullptr;
    if ((size_t)out_size >= (size_t)NTOK * HDIM + (size_t)NTOK * NEXP)
        logits_out = out + (size_t)NTOK * HDIM;

    // conversions
    convert_x_kernel<<<4096, 256>>>(x);
    transpose_convert_kernel<<<dim3(FDIM / 32, HDIM / 32), 256>>>(w1, b1, HDIM, FDIM);
    transpose_convert_kernel<<<dim3(FDIM / 32, HDIM / 32), 256>>>(w3, b3, HDIM, FDIM);
    transpose_convert_kernel<<<dim3(HDIM / 32, FDIM / 32), 256>>>(w2, b2, FDIM, HDIM);

    // router + LoRA coefficients; LoRA GEMM initializes out (beta=0)
    router_lora_kernel<<<NTOK, 128>>>(x, router_w, lora_A, logits_out);
    sgemm128_kernel<<<dim3(HDIM / 128, NTOK / 128), 256>>>(cc, lora_B, out, NTOK, HDIM, NEXP * NR);

    // GEMM1: h1 = x @ w1 (fp32 gate)
    gemm_f16_kernel<<<dim3(FDIM / 128, NTOK / 128), 256, GEMM_SMEM>>>(
        xh, b1, h1, nullptr, nullptr, HDIM, 0);

    // GEMM3 + fused silu-mul: a2 = fp16(silu(h1) * (x @ w3))
    gemm_f16_kernel<<<dim3(FDIM / 128, NTOK / 128), 256, GEMM_SMEM>>>(
        xh, b3, nullptr, h1, a2, HDIM, 1);

    // GEMM2: out += a2 @ w2
    gemm_f16_kernel<<<dim3(HDIM / 128, NTOK / 128), 256, GEMM_SMEM>>>(
        a2, b2, out, nullptr, nullptr, FDIM, 2);
}